// round 2
// baseline (speedup 1.0000x reference)
#include <cuda_runtime.h>
#include <cuda_bf16.h>
#include <math.h>

#define N_NODES 50000
#define N_EDGES 800000
#define E_TOT   (N_EDGES + N_NODES)   // edges + self loops = 850000
#define F       128                   // in/out feature dim
#define HEADS   4
#define HDIM    32
#define NEG_SLOPE 0.2f

// ----------------------------------------------------------------------------
// Scratch (device globals; no allocation allowed)
// ----------------------------------------------------------------------------
__device__ float g_x0[N_NODES * F];     // layer ping buffer
__device__ float g_x1[N_NODES * F];     // layer pong buffer
__device__ float g_h [N_NODES * F];     // h = x @ W
__device__ float g_as[N_NODES * HEADS]; // alpha_src per node
__device__ float g_ad[N_NODES * HEADS]; // alpha_dst per node
__device__ float g_den[N_NODES * HEADS];// softmax denominator
__device__ int   g_deg[N_NODES];
__device__ int   g_off[N_NODES + 1];
__device__ int   g_cur[N_NODES];
__device__ int   g_csr[E_TOT];          // src node per CSR slot (grouped by dst)
__device__ float g_p  [E_TOT * HEADS];  // e logits -> exp(e - max) per edge

// ----------------------------------------------------------------------------
// CSR construction (edge_index is int32: JAX default config downcasts int64)
// ----------------------------------------------------------------------------
__global__ void zero_deg_kernel(int* deg) {
    int i = blockIdx.x * blockDim.x + threadIdx.x;
    if (i < N_NODES) deg[i] = 0;
}

__global__ void hist_kernel(const int* __restrict__ ei, int* __restrict__ deg) {
    int i = blockIdx.x * blockDim.x + threadIdx.x;
    if (i >= E_TOT) return;
    int dst = (i < N_EDGES) ? ei[N_EDGES + i] : (i - N_EDGES);
    if (dst >= 0 && dst < N_NODES) atomicAdd(&deg[dst], 1);
}

// single-block exclusive scan over 50000 degrees
__global__ void scan_kernel(const int* __restrict__ deg, int* __restrict__ off,
                            int* __restrict__ cur) {
    __shared__ int part[1024];
    const int CH = (N_NODES + 1023) / 1024;  // 49
    int t = threadIdx.x;
    int b = t * CH;
    int e = min(b + CH, N_NODES);
    int s = 0;
    for (int i = b; i < e; i++) s += deg[i];
    part[t] = s;
    __syncthreads();
    for (int o = 1; o < 1024; o <<= 1) {
        int v = (t >= o) ? part[t - o] : 0;
        __syncthreads();
        part[t] += v;
        __syncthreads();
    }
    int run = (t == 0) ? 0 : part[t - 1];
    for (int i = b; i < e; i++) {
        off[i] = run;
        cur[i] = run;
        run += deg[i];
    }
    if (t == 0) off[N_NODES] = part[1023];
}

__global__ void fill_kernel(const int* __restrict__ ei, int* __restrict__ cur,
                            int* __restrict__ csr) {
    int i = blockIdx.x * blockDim.x + threadIdx.x;
    if (i >= E_TOT) return;
    int src, dst;
    if (i < N_EDGES) { src = ei[i]; dst = ei[N_EDGES + i]; }
    else             { src = i - N_EDGES; dst = src; }
    if (dst < 0 || dst >= N_NODES) return;          // consistent with hist guard
    if (src < 0) src = 0; if (src >= N_NODES) src = N_NODES - 1;
    int pos = atomicAdd(&cur[dst], 1);
    csr[pos] = src;
}

// ----------------------------------------------------------------------------
// GEMM: h[N,128] = x[N,128] @ W[128,128].  64-row tile, 256 threads,
// thread = (t_row 0..7 rows-octet, t_col 0..31 -> 4 cols). W rows hit L1.
// ----------------------------------------------------------------------------
__global__ __launch_bounds__(256) void gemm_kernel(
    const float* __restrict__ x, const float* __restrict__ W,
    float* __restrict__ h) {
    __shared__ float xs[64 * F];
    int t = threadIdx.x;
    int row0 = blockIdx.x * 64;

    const float4* x4 = reinterpret_cast<const float4*>(x);
    float4* xs4 = reinterpret_cast<float4*>(xs);
#pragma unroll
    for (int i = 0; i < 8; i++) {
        int idx = t + i * 256;          // 0..2047 float4 slots
        int r = idx >> 5;               // 32 float4 per row
        int cc = idx & 31;
        float4 v = make_float4(0.f, 0.f, 0.f, 0.f);
        if (row0 + r < N_NODES) v = x4[(size_t)(row0 + r) * 32 + cc];
        xs4[idx] = v;
    }
    __syncthreads();

    int t_row = t >> 5, t_col = t & 31;
    float acc[8][4];
#pragma unroll
    for (int r = 0; r < 8; r++)
#pragma unroll
        for (int j = 0; j < 4; j++) acc[r][j] = 0.f;

    const float4* W4 = reinterpret_cast<const float4*>(W);
#pragma unroll 8
    for (int k = 0; k < F; k++) {
        float4 w = W4[k * 32 + t_col];
#pragma unroll
        for (int r = 0; r < 8; r++) {
            float xv = xs[(t_row * 8 + r) * F + k];
            acc[r][0] += xv * w.x;
            acc[r][1] += xv * w.y;
            acc[r][2] += xv * w.z;
            acc[r][3] += xv * w.w;
        }
    }

    float4* h4 = reinterpret_cast<float4*>(h);
#pragma unroll
    for (int r = 0; r < 8; r++) {
        int row = row0 + t_row * 8 + r;
        if (row < N_NODES)
            h4[(size_t)row * 32 + t_col] =
                make_float4(acc[r][0], acc[r][1], acc[r][2], acc[r][3]);
    }
}

// ----------------------------------------------------------------------------
// Per-node attention dots: alpha_s[n,h] = <h[n,h,:], a_s[h,:]>, same for a_d.
// One block of 128 threads per node; warp w == head w.
// ----------------------------------------------------------------------------
__global__ void alpha_kernel(const float* __restrict__ h,
                             const float* __restrict__ a_s,
                             const float* __restrict__ a_d,
                             float* __restrict__ out_s,
                             float* __restrict__ out_d) {
    int n = blockIdx.x;
    int t = threadIdx.x;
    int w = t >> 5, c = t & 31;
    float hv = h[(size_t)n * F + t];
    float s1 = hv * a_s[w * HDIM + c];
    float s2 = hv * a_d[w * HDIM + c];
#pragma unroll
    for (int o = 16; o; o >>= 1) {
        s1 += __shfl_xor_sync(0xffffffffu, s1, o);
        s2 += __shfl_xor_sync(0xffffffffu, s2, o);
    }
    if (c == 0) {
        out_s[n * HEADS + w] = s1;
        out_d[n * HEADS + w] = s2;
    }
}

// ----------------------------------------------------------------------------
// Segment softmax (per-dst): one warp per node.
// Pass 1: logits + leaky relu + max.  Pass 2: exp(e - max), store p, sum.
// Division by denom deferred to aggregation.
// ----------------------------------------------------------------------------
__global__ __launch_bounds__(256) void softmax_kernel(
    const int* __restrict__ off, const int* __restrict__ csr,
    const float* __restrict__ as, const float* __restrict__ ad,
    float* __restrict__ p, float* __restrict__ den) {
    int warp = threadIdx.x >> 5;
    int lane = threadIdx.x & 31;
    int n = blockIdx.x * 8 + warp;
    if (n >= N_NODES) return;

    int s0 = off[n], s1 = off[n + 1];
    const float4* as4 = reinterpret_cast<const float4*>(as);
    float4* p4 = reinterpret_cast<float4*>(p);
    float4 adv = reinterpret_cast<const float4*>(ad)[n];

    float m0 = -3.4e38f, m1 = -3.4e38f, m2 = -3.4e38f, m3 = -3.4e38f;
    for (int pos = s0 + lane; pos < s1; pos += 32) {
        int src = csr[pos];
        float4 av = as4[src];
        float e0 = av.x + adv.x; e0 = e0 > 0.f ? e0 : NEG_SLOPE * e0;
        float e1 = av.y + adv.y; e1 = e1 > 0.f ? e1 : NEG_SLOPE * e1;
        float e2 = av.z + adv.z; e2 = e2 > 0.f ? e2 : NEG_SLOPE * e2;
        float e3 = av.w + adv.w; e3 = e3 > 0.f ? e3 : NEG_SLOPE * e3;
        p4[pos] = make_float4(e0, e1, e2, e3);
        m0 = fmaxf(m0, e0); m1 = fmaxf(m1, e1);
        m2 = fmaxf(m2, e2); m3 = fmaxf(m3, e3);
    }
#pragma unroll
    for (int o = 16; o; o >>= 1) {
        m0 = fmaxf(m0, __shfl_xor_sync(0xffffffffu, m0, o));
        m1 = fmaxf(m1, __shfl_xor_sync(0xffffffffu, m1, o));
        m2 = fmaxf(m2, __shfl_xor_sync(0xffffffffu, m2, o));
        m3 = fmaxf(m3, __shfl_xor_sync(0xffffffffu, m3, o));
    }
    float d0 = 0.f, d1 = 0.f, d2 = 0.f, d3 = 0.f;
    for (int pos = s0 + lane; pos < s1; pos += 32) {
        float4 e = p4[pos];
        float q0 = expf(e.x - m0);
        float q1 = expf(e.y - m1);
        float q2 = expf(e.z - m2);
        float q3 = expf(e.w - m3);
        p4[pos] = make_float4(q0, q1, q2, q3);
        d0 += q0; d1 += q1; d2 += q2; d3 += q3;
    }
#pragma unroll
    for (int o = 16; o; o >>= 1) {
        d0 += __shfl_xor_sync(0xffffffffu, d0, o);
        d1 += __shfl_xor_sync(0xffffffffu, d1, o);
        d2 += __shfl_xor_sync(0xffffffffu, d2, o);
        d3 += __shfl_xor_sync(0xffffffffu, d3, o);
    }
    if (lane == 0) {
        den[n * HEADS + 0] = d0;
        den[n * HEADS + 1] = d1;
        den[n * HEADS + 2] = d2;
        den[n * HEADS + 3] = d3;
    }
}

// ----------------------------------------------------------------------------
// Aggregation: out[n,c] = relu( (sum_e p[e,head] * h[src_e, c]) / den[n,head]
//                               + bias[c] )
// One block of 128 threads per dst node; gather + register accumulate.
// ----------------------------------------------------------------------------
__global__ __launch_bounds__(128) void agg_kernel(
    const float* __restrict__ h, const int* __restrict__ off,
    const int* __restrict__ csr, const float* __restrict__ p,
    const float* __restrict__ den, const float* __restrict__ bias,
    float* __restrict__ out) {
    int n = blockIdx.x;
    int c = threadIdx.x;
    int head = c >> 5;
    int s0 = off[n], s1 = off[n + 1];
    float acc = 0.f;
    for (int pos = s0; pos < s1; pos++) {
        int src = csr[pos];
        float pv = p[pos * HEADS + head];
        acc += pv * h[(size_t)src * F + c];
    }
    float d = den[n * HEADS + head];
    float inv = (d != 0.f) ? 1.f / d : 0.f;
    float o = acc * inv + bias[c];
    out[(size_t)n * F + c] = o > 0.f ? o : 0.f;
}

// ----------------------------------------------------------------------------
// Launch
// ----------------------------------------------------------------------------
extern "C" void kernel_launch(void* const* d_in, const int* in_sizes, int n_in,
                              void* d_out, int out_size) {
    const float* x    = (const float*)d_in[0];
    const int*   ei   = (const int*)d_in[1];
    const float* Ws   = (const float*)d_in[2];
    const float* a_s  = (const float*)d_in[3];
    const float* a_d  = (const float*)d_in[4];
    const float* bias = (const float*)d_in[5];
    float*       out  = (float*)d_out;

    void* pv;
    cudaGetSymbolAddress(&pv, g_x0);  float* x0  = (float*)pv;
    cudaGetSymbolAddress(&pv, g_x1);  float* x1  = (float*)pv;
    cudaGetSymbolAddress(&pv, g_h);   float* h   = (float*)pv;
    cudaGetSymbolAddress(&pv, g_as);  float* as  = (float*)pv;
    cudaGetSymbolAddress(&pv, g_ad);  float* ad  = (float*)pv;
    cudaGetSymbolAddress(&pv, g_den); float* den = (float*)pv;
    cudaGetSymbolAddress(&pv, g_deg); int*   deg = (int*)pv;
    cudaGetSymbolAddress(&pv, g_off); int*   off = (int*)pv;
    cudaGetSymbolAddress(&pv, g_cur); int*   cur = (int*)pv;
    cudaGetSymbolAddress(&pv, g_csr); int*   csr = (int*)pv;
    cudaGetSymbolAddress(&pv, g_p);   float* p   = (float*)pv;

    // CSR build (once; reused by all 3 layers)
    zero_deg_kernel<<<(N_NODES + 255) / 256, 256>>>(deg);
    hist_kernel<<<(E_TOT + 255) / 256, 256>>>(ei, deg);
    scan_kernel<<<1, 1024>>>(deg, off, cur);
    fill_kernel<<<(E_TOT + 255) / 256, 256>>>(ei, cur, csr);

    for (int l = 0; l < 3; l++) {
        const float* xin = (l == 0) ? x : ((l == 1) ? x0 : x1);
        float* xout = (l == 0) ? x0 : ((l == 1) ? x1 : out);
        gemm_kernel<<<(N_NODES + 63) / 64, 256>>>(xin, Ws + (size_t)l * F * F, h);
        alpha_kernel<<<N_NODES, 128>>>(h, a_s + l * F, a_d + l * F, as, ad);
        softmax_kernel<<<(N_NODES + 7) / 8, 256>>>(off, csr, as, ad, p, den);
        agg_kernel<<<N_NODES, 128>>>(h, off, csr, p, den, bias + l * F, xout);
    }
}

// round 3
// speedup vs baseline: 1.1784x; 1.1784x over previous
#include <cuda_runtime.h>
#include <cuda_bf16.h>
#include <math.h>

#define N_NODES 50000
#define N_EDGES 800000
#define E_TOT   (N_EDGES + N_NODES)   // edges + self loops = 850000
#define F       128                   // in/out feature dim
#define HEADS   4
#define HDIM    32
#define NEG_SLOPE 0.2f

// ----------------------------------------------------------------------------
// Scratch (device globals; no allocation allowed)
// ----------------------------------------------------------------------------
__device__ float g_x0[N_NODES * F];     // layer ping buffer
__device__ float g_x1[N_NODES * F];     // layer pong buffer
__device__ float g_h [N_NODES * F];     // h = x @ W
__device__ float g_as[N_NODES * HEADS]; // alpha_src per node
__device__ float g_ad[N_NODES * HEADS]; // alpha_dst per node
__device__ float g_den[N_NODES * HEADS];// softmax denominator
__device__ int   g_deg[N_NODES];
__device__ int   g_off[N_NODES + 1];
__device__ int   g_cur[N_NODES];
__device__ int   g_csr[E_TOT];          // src node per CSR slot (grouped by dst)
__device__ float g_p  [E_TOT * HEADS];  // exp(leaky(e)) per edge per head

// ----------------------------------------------------------------------------
// Packed fp32x2 helpers (Blackwell: FFMA2 only reachable via PTX fma.rn.f32x2)
// ----------------------------------------------------------------------------
__device__ __forceinline__ unsigned long long pack2(float lo, float hi) {
    unsigned long long r;
    asm("mov.b64 %0, {%1, %2};" : "=l"(r) : "f"(lo), "f"(hi));
    return r;
}
__device__ __forceinline__ void unpack2(unsigned long long v, float& lo, float& hi) {
    asm("mov.b64 {%0, %1}, %2;" : "=f"(lo), "=f"(hi) : "l"(v));
}
#define FMA2(d, a, b) asm("fma.rn.f32x2 %0, %1, %2, %0;" : "+l"(d) : "l"(a), "l"(b))

// ----------------------------------------------------------------------------
// CSR construction (edge_index is int32)
// ----------------------------------------------------------------------------
__global__ void zero_deg_kernel(int* deg) {
    int i = blockIdx.x * blockDim.x + threadIdx.x;
    if (i < N_NODES) deg[i] = 0;
}

__global__ void hist_kernel(const int* __restrict__ ei, int* __restrict__ deg) {
    int i = blockIdx.x * blockDim.x + threadIdx.x;
    if (i >= E_TOT) return;
    int dst = (i < N_EDGES) ? ei[N_EDGES + i] : (i - N_EDGES);
    if (dst >= 0 && dst < N_NODES) atomicAdd(&deg[dst], 1);
}

// single-block exclusive scan over 50000 degrees
__global__ void scan_kernel(const int* __restrict__ deg, int* __restrict__ off,
                            int* __restrict__ cur) {
    __shared__ int part[1024];
    const int CH = (N_NODES + 1023) / 1024;  // 49
    int t = threadIdx.x;
    int b = t * CH;
    int e = min(b + CH, N_NODES);
    int s = 0;
    for (int i = b; i < e; i++) s += deg[i];
    part[t] = s;
    __syncthreads();
    for (int o = 1; o < 1024; o <<= 1) {
        int v = (t >= o) ? part[t - o] : 0;
        __syncthreads();
        part[t] += v;
        __syncthreads();
    }
    int run = (t == 0) ? 0 : part[t - 1];
    for (int i = b; i < e; i++) {
        off[i] = run;
        cur[i] = run;
        run += deg[i];
    }
    if (t == 0) off[N_NODES] = part[1023];
}

__global__ void fill_kernel(const int* __restrict__ ei, int* __restrict__ cur,
                            int* __restrict__ csr) {
    int i = blockIdx.x * blockDim.x + threadIdx.x;
    if (i >= E_TOT) return;
    int src, dst;
    if (i < N_EDGES) { src = ei[i]; dst = ei[N_EDGES + i]; }
    else             { src = i - N_EDGES; dst = src; }
    if (dst < 0 || dst >= N_NODES) return;
    if (src < 0) src = 0; if (src >= N_NODES) src = N_NODES - 1;
    int pos = atomicAdd(&cur[dst], 1);
    csr[pos] = src;
}

// ----------------------------------------------------------------------------
// GEMM + alpha fusion: h[N,128] = x[N,128] @ W[128,128], then
// as[n,head] = <h[n,head,:], a_s[head,:]> (same for ad) via 8-lane butterfly.
// 64-row tile, 256 threads. Inner product uses packed fma.rn.f32x2.
// ----------------------------------------------------------------------------
__global__ __launch_bounds__(256) void gemm_alpha_kernel(
    const float* __restrict__ x, const float* __restrict__ W,
    const float* __restrict__ a_s, const float* __restrict__ a_d,
    float* __restrict__ h, float* __restrict__ out_s, float* __restrict__ out_d) {
    __shared__ float xs[64 * F];
    int t = threadIdx.x;
    int row0 = blockIdx.x * 64;

    const float4* x4 = reinterpret_cast<const float4*>(x);
    float4* xs4 = reinterpret_cast<float4*>(xs);
#pragma unroll
    for (int i = 0; i < 8; i++) {
        int idx = t + i * 256;          // 0..2047 float4 slots
        int r = idx >> 5;
        int cc = idx & 31;
        float4 v = make_float4(0.f, 0.f, 0.f, 0.f);
        if (row0 + r < N_NODES) v = x4[(size_t)(row0 + r) * 32 + cc];
        xs4[idx] = v;
    }
    __syncthreads();

    int t_row = t >> 5, t_col = t & 31;

    unsigned long long acc2[4][4];  // [row-pair][col j]; each = (row 2rr, row 2rr+1)
#pragma unroll
    for (int rr = 0; rr < 4; rr++)
#pragma unroll
        for (int j = 0; j < 4; j++) acc2[rr][j] = pack2(0.f, 0.f);

    const float4* W4 = reinterpret_cast<const float4*>(W);
    const float* xbase = xs + t_row * 8 * F;
#pragma unroll 4
    for (int k = 0; k < F; k++) {
        float4 w = W4[k * 32 + t_col];
        unsigned long long w0 = pack2(w.x, w.x);
        unsigned long long w1 = pack2(w.y, w.y);
        unsigned long long w2 = pack2(w.z, w.z);
        unsigned long long w3 = pack2(w.w, w.w);
#pragma unroll
        for (int rr = 0; rr < 4; rr++) {
            float xa = xbase[(2 * rr) * F + k];     // LDS broadcast (warp-uniform)
            float xb = xbase[(2 * rr + 1) * F + k];
            unsigned long long xp = pack2(xa, xb);
            FMA2(acc2[rr][0], xp, w0);
            FMA2(acc2[rr][1], xp, w1);
            FMA2(acc2[rr][2], xp, w2);
            FMA2(acc2[rr][3], xp, w3);
        }
    }

    // unpack
    float accf[8][4];
#pragma unroll
    for (int rr = 0; rr < 4; rr++)
#pragma unroll
        for (int j = 0; j < 4; j++)
            unpack2(acc2[rr][j], accf[2 * rr][j], accf[2 * rr + 1][j]);

    // store h
    float4* h4 = reinterpret_cast<float4*>(h);
#pragma unroll
    for (int r = 0; r < 8; r++) {
        int row = row0 + t_row * 8 + r;
        if (row < N_NODES)
            h4[(size_t)row * 32 + t_col] =
                make_float4(accf[r][0], accf[r][1], accf[r][2], accf[r][3]);
    }

    // fused alpha: channels of head hd live in lanes t_col = 8*hd .. 8*hd+7
    float4 asv = reinterpret_cast<const float4*>(a_s)[t_col];
    float4 adv = reinterpret_cast<const float4*>(a_d)[t_col];
    int head = t_col >> 3;
#pragma unroll
    for (int r = 0; r < 8; r++) {
        int row = row0 + t_row * 8 + r;
        float ps = accf[r][0] * asv.x + accf[r][1] * asv.y +
                   accf[r][2] * asv.z + accf[r][3] * asv.w;
        float pd = accf[r][0] * adv.x + accf[r][1] * adv.y +
                   accf[r][2] * adv.z + accf[r][3] * adv.w;
#pragma unroll
        for (int o = 1; o < 8; o <<= 1) {
            ps += __shfl_xor_sync(0xffffffffu, ps, o);
            pd += __shfl_xor_sync(0xffffffffu, pd, o);
        }
        if ((t_col & 7) == 0 && row < N_NODES) {
            out_s[row * HEADS + head] = ps;
            out_d[row * HEADS + head] = pd;
        }
    }
}

// ----------------------------------------------------------------------------
// Edge weights: single pass (softmax is shift-invariant; logits are O(10),
// far from fp32 exp overflow, so no segment-max needed).
// p[pos,h] = exp(leaky(as[src,h] + ad[n,h])); den[n,h] = sum of p.
// One warp per dst node.
// ----------------------------------------------------------------------------
__global__ __launch_bounds__(256) void edge_p_kernel(
    const int* __restrict__ off, const int* __restrict__ csr,
    const float* __restrict__ as, const float* __restrict__ ad,
    float* __restrict__ p, float* __restrict__ den) {
    int warp = threadIdx.x >> 5;
    int lane = threadIdx.x & 31;
    int n = blockIdx.x * 8 + warp;
    if (n >= N_NODES) return;

    int s0 = off[n], s1 = off[n + 1];
    const float4* as4 = reinterpret_cast<const float4*>(as);
    float4* p4 = reinterpret_cast<float4*>(p);
    float4 adv = reinterpret_cast<const float4*>(ad)[n];

    float d0 = 0.f, d1 = 0.f, d2 = 0.f, d3 = 0.f;
    for (int pos = s0 + lane; pos < s1; pos += 32) {
        int src = csr[pos];
        float4 av = as4[src];
        float e0 = av.x + adv.x; e0 = e0 > 0.f ? e0 : NEG_SLOPE * e0;
        float e1 = av.y + adv.y; e1 = e1 > 0.f ? e1 : NEG_SLOPE * e1;
        float e2 = av.z + adv.z; e2 = e2 > 0.f ? e2 : NEG_SLOPE * e2;
        float e3 = av.w + adv.w; e3 = e3 > 0.f ? e3 : NEG_SLOPE * e3;
        float q0 = expf(e0), q1 = expf(e1), q2 = expf(e2), q3 = expf(e3);
        p4[pos] = make_float4(q0, q1, q2, q3);
        d0 += q0; d1 += q1; d2 += q2; d3 += q3;
    }
#pragma unroll
    for (int o = 16; o; o >>= 1) {
        d0 += __shfl_xor_sync(0xffffffffu, d0, o);
        d1 += __shfl_xor_sync(0xffffffffu, d1, o);
        d2 += __shfl_xor_sync(0xffffffffu, d2, o);
        d3 += __shfl_xor_sync(0xffffffffu, d3, o);
    }
    if (lane == 0) {
        den[n * HEADS + 0] = d0;
        den[n * HEADS + 1] = d1;
        den[n * HEADS + 2] = d2;
        den[n * HEADS + 3] = d3;
    }
}

// ----------------------------------------------------------------------------
// Aggregation: out[n,c] = relu( (sum_e p[e,head] * h[src_e, c]) / den[n,head]
//                               + bias[c] ).  Edge loop unrolled x4 for MLP.
// ----------------------------------------------------------------------------
__global__ __launch_bounds__(128) void agg_kernel(
    const float* __restrict__ h, const int* __restrict__ off,
    const int* __restrict__ csr, const float* __restrict__ p,
    const float* __restrict__ den, const float* __restrict__ bias,
    float* __restrict__ out) {
    int n = blockIdx.x;
    int c = threadIdx.x;
    int head = c >> 5;
    int s0 = off[n], s1 = off[n + 1];

    float acc0 = 0.f, acc1 = 0.f, acc2 = 0.f, acc3 = 0.f;
    int pos = s0;
    for (; pos + 4 <= s1; pos += 4) {
        int a = csr[pos], b = csr[pos + 1], cc = csr[pos + 2], d = csr[pos + 3];
        float pa = p[(size_t)pos * HEADS + head];
        float pb = p[(size_t)(pos + 1) * HEADS + head];
        float pc = p[(size_t)(pos + 2) * HEADS + head];
        float pd = p[(size_t)(pos + 3) * HEADS + head];
        acc0 += pa * h[(size_t)a * F + c];
        acc1 += pb * h[(size_t)b * F + c];
        acc2 += pc * h[(size_t)cc * F + c];
        acc3 += pd * h[(size_t)d * F + c];
    }
    for (; pos < s1; pos++) {
        int a = csr[pos];
        acc0 += p[(size_t)pos * HEADS + head] * h[(size_t)a * F + c];
    }
    float acc = (acc0 + acc1) + (acc2 + acc3);
    float dsum = den[n * HEADS + head];
    float inv = (dsum != 0.f) ? 1.f / dsum : 0.f;
    float o = acc * inv + bias[c];
    out[(size_t)n * F + c] = o > 0.f ? o : 0.f;
}

// ----------------------------------------------------------------------------
// Launch
// ----------------------------------------------------------------------------
extern "C" void kernel_launch(void* const* d_in, const int* in_sizes, int n_in,
                              void* d_out, int out_size) {
    const float* x    = (const float*)d_in[0];
    const int*   ei   = (const int*)d_in[1];
    const float* Ws   = (const float*)d_in[2];
    const float* a_s  = (const float*)d_in[3];
    const float* a_d  = (const float*)d_in[4];
    const float* bias = (const float*)d_in[5];
    float*       out  = (float*)d_out;

    void* pv;
    cudaGetSymbolAddress(&pv, g_x0);  float* x0  = (float*)pv;
    cudaGetSymbolAddress(&pv, g_x1);  float* x1  = (float*)pv;
    cudaGetSymbolAddress(&pv, g_h);   float* h   = (float*)pv;
    cudaGetSymbolAddress(&pv, g_as);  float* as  = (float*)pv;
    cudaGetSymbolAddress(&pv, g_ad);  float* ad  = (float*)pv;
    cudaGetSymbolAddress(&pv, g_den); float* den = (float*)pv;
    cudaGetSymbolAddress(&pv, g_deg); int*   deg = (int*)pv;
    cudaGetSymbolAddress(&pv, g_off); int*   off = (int*)pv;
    cudaGetSymbolAddress(&pv, g_cur); int*   cur = (int*)pv;
    cudaGetSymbolAddress(&pv, g_csr); int*   csr = (int*)pv;
    cudaGetSymbolAddress(&pv, g_p);   float* p   = (float*)pv;

    // CSR build (once; reused by all 3 layers)
    zero_deg_kernel<<<(N_NODES + 255) / 256, 256>>>(deg);
    hist_kernel<<<(E_TOT + 255) / 256, 256>>>(ei, deg);
    scan_kernel<<<1, 1024>>>(deg, off, cur);
    fill_kernel<<<(E_TOT + 255) / 256, 256>>>(ei, cur, csr);

    for (int l = 0; l < 3; l++) {
        const float* xin = (l == 0) ? x : ((l == 1) ? x0 : x1);
        float* xout = (l == 0) ? x0 : ((l == 1) ? x1 : out);
        gemm_alpha_kernel<<<(N_NODES + 63) / 64, 256>>>(
            xin, Ws + (size_t)l * F * F, a_s + l * F, a_d + l * F, h, as, ad);
        edge_p_kernel<<<(N_NODES + 7) / 8, 256>>>(off, csr, as, ad, p, den);
        agg_kernel<<<N_NODES, 128>>>(h, off, csr, p, den, bias + l * F, xout);
    }
}

// round 4
// speedup vs baseline: 1.5905x; 1.3497x over previous
#include <cuda_runtime.h>
#include <cuda_bf16.h>
#include <math.h>

#define N_NODES 50000
#define N_EDGES 800000
#define E_TOT   (N_EDGES + N_NODES)   // edges + self loops = 850000
#define F       128                   // in/out feature dim
#define HEADS   4
#define HDIM    32
#define NEG_SLOPE 0.2f

// ----------------------------------------------------------------------------
// Scratch (device globals; no allocation allowed)
// ----------------------------------------------------------------------------
__device__ float g_x0[N_NODES * F];     // layer ping buffer
__device__ float g_x1[N_NODES * F];     // layer pong buffer
__device__ float g_h [N_NODES * F];     // h = x @ W
__device__ float g_as[N_NODES * HEADS]; // alpha_src per node
__device__ float g_ad[N_NODES * HEADS]; // alpha_dst per node
__device__ int   g_deg[N_NODES];
__device__ int   g_off[N_NODES + 1];
__device__ int   g_cur[N_NODES];
__device__ int   g_csr[E_TOT];          // src node per CSR slot (grouped by dst)

// ----------------------------------------------------------------------------
// Packed fp32x2 helpers (Blackwell: FFMA2 only reachable via PTX fma.rn.f32x2)
// ----------------------------------------------------------------------------
__device__ __forceinline__ unsigned long long pack2(float lo, float hi) {
    unsigned long long r;
    asm("mov.b64 %0, {%1, %2};" : "=l"(r) : "f"(lo), "f"(hi));
    return r;
}
__device__ __forceinline__ void unpack2(unsigned long long v, float& lo, float& hi) {
    asm("mov.b64 {%0, %1}, %2;" : "=f"(lo), "=f"(hi) : "l"(v));
}
#define FMA2(d, a, b) asm("fma.rn.f32x2 %0, %1, %2, %0;" : "+l"(d) : "l"(a), "l"(b))

// ----------------------------------------------------------------------------
// CSR construction (edge_index is int32)
// ----------------------------------------------------------------------------
__global__ void zero_deg_kernel(int* deg) {
    int i = blockIdx.x * blockDim.x + threadIdx.x;
    if (i < N_NODES) deg[i] = 0;
}

__global__ void hist_kernel(const int* __restrict__ ei, int* __restrict__ deg) {
    int i = blockIdx.x * blockDim.x + threadIdx.x;
    if (i >= E_TOT) return;
    int dst = (i < N_EDGES) ? ei[N_EDGES + i] : (i - N_EDGES);
    if (dst >= 0 && dst < N_NODES) atomicAdd(&deg[dst], 1);
}

// single-block exclusive scan over 50000 degrees
__global__ void scan_kernel(const int* __restrict__ deg, int* __restrict__ off,
                            int* __restrict__ cur) {
    __shared__ int part[1024];
    const int CH = (N_NODES + 1023) / 1024;  // 49
    int t = threadIdx.x;
    int b = t * CH;
    int e = min(b + CH, N_NODES);
    int s = 0;
    for (int i = b; i < e; i++) s += deg[i];
    part[t] = s;
    __syncthreads();
    for (int o = 1; o < 1024; o <<= 1) {
        int v = (t >= o) ? part[t - o] : 0;
        __syncthreads();
        part[t] += v;
        __syncthreads();
    }
    int run = (t == 0) ? 0 : part[t - 1];
    for (int i = b; i < e; i++) {
        off[i] = run;
        cur[i] = run;
        run += deg[i];
    }
    if (t == 0) off[N_NODES] = part[1023];
}

__global__ void fill_kernel(const int* __restrict__ ei, int* __restrict__ cur,
                            int* __restrict__ csr) {
    int i = blockIdx.x * blockDim.x + threadIdx.x;
    if (i >= E_TOT) return;
    int src, dst;
    if (i < N_EDGES) { src = ei[i]; dst = ei[N_EDGES + i]; }
    else             { src = i - N_EDGES; dst = src; }
    if (dst < 0 || dst >= N_NODES) return;
    if (src < 0) src = 0; if (src >= N_NODES) src = N_NODES - 1;
    int pos = atomicAdd(&cur[dst], 1);
    csr[pos] = src;
}

// ----------------------------------------------------------------------------
// GEMM + alpha fusion: h[N,128] = x[N,128] @ W[128,128], then
// as[n,head] = <h[n,head,:], a_s[head,:]> (same for ad) via 8-lane butterfly.
// 64-row tile, 256 threads. Inner product uses packed fma.rn.f32x2.
// ----------------------------------------------------------------------------
__global__ __launch_bounds__(256) void gemm_alpha_kernel(
    const float* __restrict__ x, const float* __restrict__ W,
    const float* __restrict__ a_s, const float* __restrict__ a_d,
    float* __restrict__ h, float* __restrict__ out_s, float* __restrict__ out_d) {
    __shared__ float xs[64 * F];
    int t = threadIdx.x;
    int row0 = blockIdx.x * 64;

    const float4* x4 = reinterpret_cast<const float4*>(x);
    float4* xs4 = reinterpret_cast<float4*>(xs);
#pragma unroll
    for (int i = 0; i < 8; i++) {
        int idx = t + i * 256;          // 0..2047 float4 slots
        int r = idx >> 5;
        int cc = idx & 31;
        float4 v = make_float4(0.f, 0.f, 0.f, 0.f);
        if (row0 + r < N_NODES) v = x4[(size_t)(row0 + r) * 32 + cc];
        xs4[idx] = v;
    }
    __syncthreads();

    int t_row = t >> 5, t_col = t & 31;

    unsigned long long acc2[4][4];  // [row-pair][col j]; each = (row 2rr, row 2rr+1)
#pragma unroll
    for (int rr = 0; rr < 4; rr++)
#pragma unroll
        for (int j = 0; j < 4; j++) acc2[rr][j] = pack2(0.f, 0.f);

    const float4* W4 = reinterpret_cast<const float4*>(W);
    const float* xbase = xs + t_row * 8 * F;
#pragma unroll 4
    for (int k = 0; k < F; k++) {
        float4 w = W4[k * 32 + t_col];
        unsigned long long w0 = pack2(w.x, w.x);
        unsigned long long w1 = pack2(w.y, w.y);
        unsigned long long w2 = pack2(w.z, w.z);
        unsigned long long w3 = pack2(w.w, w.w);
#pragma unroll
        for (int rr = 0; rr < 4; rr++) {
            float xa = xbase[(2 * rr) * F + k];     // LDS broadcast (warp-uniform)
            float xb = xbase[(2 * rr + 1) * F + k];
            unsigned long long xp = pack2(xa, xb);
            FMA2(acc2[rr][0], xp, w0);
            FMA2(acc2[rr][1], xp, w1);
            FMA2(acc2[rr][2], xp, w2);
            FMA2(acc2[rr][3], xp, w3);
        }
    }

    // unpack
    float accf[8][4];
#pragma unroll
    for (int rr = 0; rr < 4; rr++)
#pragma unroll
        for (int j = 0; j < 4; j++)
            unpack2(acc2[rr][j], accf[2 * rr][j], accf[2 * rr + 1][j]);

    // store h
    float4* h4 = reinterpret_cast<float4*>(h);
#pragma unroll
    for (int r = 0; r < 8; r++) {
        int row = row0 + t_row * 8 + r;
        if (row < N_NODES)
            h4[(size_t)row * 32 + t_col] =
                make_float4(accf[r][0], accf[r][1], accf[r][2], accf[r][3]);
    }

    // fused alpha: channels of head hd live in lanes t_col = 8*hd .. 8*hd+7
    float4 asv = reinterpret_cast<const float4*>(a_s)[t_col];
    float4 adv = reinterpret_cast<const float4*>(a_d)[t_col];
    int head = t_col >> 3;
#pragma unroll
    for (int r = 0; r < 8; r++) {
        int row = row0 + t_row * 8 + r;
        float ps = accf[r][0] * asv.x + accf[r][1] * asv.y +
                   accf[r][2] * asv.z + accf[r][3] * asv.w;
        float pd = accf[r][0] * adv.x + accf[r][1] * adv.y +
                   accf[r][2] * adv.z + accf[r][3] * adv.w;
#pragma unroll
        for (int o = 1; o < 8; o <<= 1) {
            ps += __shfl_xor_sync(0xffffffffu, ps, o);
            pd += __shfl_xor_sync(0xffffffffu, pd, o);
        }
        if ((t_col & 7) == 0 && row < N_NODES) {
            out_s[row * HEADS + head] = ps;
            out_d[row * HEADS + head] = pd;
        }
    }
}

// ----------------------------------------------------------------------------
// Fused softmax + aggregation: one warp per dst node.
// Lanes split channels: lane covers c = 4*lane..4*lane+3; head = lane>>3.
// Whole warp walks each edge together:
//   q = exp(leaky(as[src,head] + ad[n,head]))   (identical in all 8 lanes of a head)
//   acc4 += q * h[src, 4*lane..]; den += q      (den identical per head -> no reduce)
// out[n,c] = relu(acc/den + bias[c])
// Softmax shift dropped (shift-invariant; logits O(10) << exp overflow).
// ----------------------------------------------------------------------------
__global__ __launch_bounds__(256) void agg_fused_kernel(
    const float* __restrict__ h, const int* __restrict__ off,
    const int* __restrict__ csr, const float* __restrict__ as,
    const float* __restrict__ ad, const float* __restrict__ bias,
    float* __restrict__ out) {
    int warp = threadIdx.x >> 5;
    int lane = threadIdx.x & 31;
    int n = blockIdx.x * 8 + warp;
    if (n >= N_NODES) return;

    int head = lane >> 3;
    float ad_h = ad[n * HEADS + head];
    const float4* h4 = reinterpret_cast<const float4*>(h);

    float4 acc = make_float4(0.f, 0.f, 0.f, 0.f);
    float den = 0.f;
    int s0 = off[n], s1 = off[n + 1];

    int pos = s0;
    for (; pos + 4 <= s1; pos += 4) {
        int sa = csr[pos];       // broadcast loads (same addr across warp)
        int sb = csr[pos + 1];
        int sc = csr[pos + 2];
        int sd = csr[pos + 3];
        float ea = as[sa * HEADS + head] + ad_h;
        float eb = as[sb * HEADS + head] + ad_h;
        float ec = as[sc * HEADS + head] + ad_h;
        float ed = as[sd * HEADS + head] + ad_h;
        ea = ea > 0.f ? ea : NEG_SLOPE * ea;
        eb = eb > 0.f ? eb : NEG_SLOPE * eb;
        ec = ec > 0.f ? ec : NEG_SLOPE * ec;
        ed = ed > 0.f ? ed : NEG_SLOPE * ed;
        float qa = __expf(ea), qb = __expf(eb), qc = __expf(ec), qd = __expf(ed);
        float4 ha = h4[(size_t)sa * 32 + lane];
        float4 hb = h4[(size_t)sb * 32 + lane];
        float4 hc = h4[(size_t)sc * 32 + lane];
        float4 hd = h4[(size_t)sd * 32 + lane];
        acc.x += qa * ha.x + qb * hb.x + qc * hc.x + qd * hd.x;
        acc.y += qa * ha.y + qb * hb.y + qc * hc.y + qd * hd.y;
        acc.z += qa * ha.z + qb * hb.z + qc * hc.z + qd * hd.z;
        acc.w += qa * ha.w + qb * hb.w + qc * hc.w + qd * hd.w;
        den += (qa + qb) + (qc + qd);
    }
    for (; pos < s1; pos++) {
        int sa = csr[pos];
        float e = as[sa * HEADS + head] + ad_h;
        e = e > 0.f ? e : NEG_SLOPE * e;
        float q = __expf(e);
        float4 ha = h4[(size_t)sa * 32 + lane];
        acc.x += q * ha.x; acc.y += q * ha.y;
        acc.z += q * ha.z; acc.w += q * ha.w;
        den += q;
    }

    float inv = 1.f / den;   // deg >= 1 (self loop), den > 0
    float4 bv = reinterpret_cast<const float4*>(bias)[lane];
    float4 o;
    o.x = fmaxf(acc.x * inv + bv.x, 0.f);
    o.y = fmaxf(acc.y * inv + bv.y, 0.f);
    o.z = fmaxf(acc.z * inv + bv.z, 0.f);
    o.w = fmaxf(acc.w * inv + bv.w, 0.f);
    reinterpret_cast<float4*>(out)[(size_t)n * 32 + lane] = o;
}

// ----------------------------------------------------------------------------
// Launch
// ----------------------------------------------------------------------------
extern "C" void kernel_launch(void* const* d_in, const int* in_sizes, int n_in,
                              void* d_out, int out_size) {
    const float* x    = (const float*)d_in[0];
    const int*   ei   = (const int*)d_in[1];
    const float* Ws   = (const float*)d_in[2];
    const float* a_s  = (const float*)d_in[3];
    const float* a_d  = (const float*)d_in[4];
    const float* bias = (const float*)d_in[5];
    float*       out  = (float*)d_out;

    void* pv;
    cudaGetSymbolAddress(&pv, g_x0);  float* x0  = (float*)pv;
    cudaGetSymbolAddress(&pv, g_x1);  float* x1  = (float*)pv;
    cudaGetSymbolAddress(&pv, g_h);   float* h   = (float*)pv;
    cudaGetSymbolAddress(&pv, g_as);  float* as  = (float*)pv;
    cudaGetSymbolAddress(&pv, g_ad);  float* ad  = (float*)pv;
    cudaGetSymbolAddress(&pv, g_deg); int*   deg = (int*)pv;
    cudaGetSymbolAddress(&pv, g_off); int*   off = (int*)pv;
    cudaGetSymbolAddress(&pv, g_cur); int*   cur = (int*)pv;
    cudaGetSymbolAddress(&pv, g_csr); int*   csr = (int*)pv;

    // CSR build (once; reused by all 3 layers)
    zero_deg_kernel<<<(N_NODES + 255) / 256, 256>>>(deg);
    hist_kernel<<<(E_TOT + 255) / 256, 256>>>(ei, deg);
    scan_kernel<<<1, 1024>>>(deg, off, cur);
    fill_kernel<<<(E_TOT + 255) / 256, 256>>>(ei, cur, csr);

    for (int l = 0; l < 3; l++) {
        const float* xin = (l == 0) ? x : ((l == 1) ? x0 : x1);
        float* xout = (l == 0) ? x0 : ((l == 1) ? x1 : out);
        gemm_alpha_kernel<<<(N_NODES + 63) / 64, 256>>>(
            xin, Ws + (size_t)l * F * F, a_s + l * F, a_d + l * F, h, as, ad);
        agg_fused_kernel<<<(N_NODES + 7) / 8, 256>>>(
            h, off, csr, as, ad, bias + l * F, xout);
    }
}